// round 1
// baseline (speedup 1.0000x reference)
#include <cuda_runtime.h>

// B3-spline undecimated wavelet transform (à trous), J=3, fully fused.
// Input:  x (8, 1024, 1024) fp32
// Output: (8, 4, 1024, 1024) fp32 = [w1, w2, w3, c3]
//
// One CTA = one 64x64 output tile. 96x96 shared grid (halo 14, padded to 16 so
// the center region is 16B-aligned). All 6 separable conv passes + emits done
// in shared memory; reflect padding applied once at the global load (valid
// because reflection commutes with the symmetric B3 kernel).

namespace {

constexpr int HW   = 1024;
constexpr int Sg   = 96;   // shared grid side
constexpr int PIT  = 96;   // row pitch in floats
constexpr int CEN  = 16;   // center offset inside shared grid
constexpr int TILE = 64;
constexpr int NT   = 256;  // threads per block

__device__ __forceinline__ int refl(int i) {
    if (i < 0) i = -i;
    if (i >= HW) i = 2 * HW - 2 - i;
    return i;
}

// Vertical (row-direction) 5-tap conv with dilation D.
// Each work item: 4 consecutive rows x 4 consecutive cols (float4), streaming
// the 4+4D needed input rows through one register each -> (4+4D)/4 loads/out.
template <int D>
__device__ __forceinline__ void hconv(const float* __restrict__ src,
                                      float* __restrict__ dst,
                                      int r0, int nrows, int tid) {
    const float wts[5] = {0.0625f, 0.25f, 0.375f, 0.25f, 0.0625f};
    const int NCG = Sg / 4;  // 24 col groups
    const int items = (nrows / 4) * NCG;
    for (int it = tid; it < items; it += NT) {
        const int cg = it % NCG;
        const int rg = it / NCG;
        const int x4 = cg * 4;
        const int y0 = r0 + rg * 4;
        float4 acc[4];
#pragma unroll
        for (int i = 0; i < 4; ++i) acc[i] = make_float4(0.f, 0.f, 0.f, 0.f);
#pragma unroll
        for (int rr = 0; rr < 4 + 4 * D; ++rr) {
            const float4 v =
                *reinterpret_cast<const float4*>(src + (y0 - 2 * D + rr) * PIT + x4);
#pragma unroll
            for (int i = 0; i < 4; ++i) {
                const int t = rr - i;
                if (t >= 0 && t <= 4 * D && (t % D) == 0) {
                    const float w = wts[t / D];
                    acc[i].x += w * v.x;
                    acc[i].y += w * v.y;
                    acc[i].z += w * v.z;
                    acc[i].w += w * v.w;
                }
            }
        }
#pragma unroll
        for (int i = 0; i < 4; ++i)
            *reinterpret_cast<float4*>(dst + (y0 + i) * PIT + x4) = acc[i];
    }
}

// Horizontal (col-direction) 5-tap conv with dilation D.
// Each work item: 1 row x 4 cols; loads the exact 4+4D scalar window.
// Out-of-range taps are clamped (garbage values never reach valid regions).
template <int D>
__device__ __forceinline__ void wconv(const float* __restrict__ src,
                                      float* __restrict__ dst,
                                      int r0, int nrows, int tid) {
    const float wts[5] = {0.0625f, 0.25f, 0.375f, 0.25f, 0.0625f};
    const int NCG = Sg / 4;
    const int items = nrows * NCG;
    for (int it = tid; it < items; it += NT) {
        const int cg = it % NCG;
        const int y = r0 + it / NCG;
        const int x4 = cg * 4;
        const float* row = src + y * PIT;
        float buf[4 + 4 * D];
#pragma unroll
        for (int j = 0; j < 4 + 4 * D; ++j) {
            int xx = x4 - 2 * D + j;
            xx = xx < 0 ? 0 : (xx > Sg - 1 ? Sg - 1 : xx);
            buf[j] = row[xx];
        }
        float4 o;
        float* op = reinterpret_cast<float*>(&o);
#pragma unroll
        for (int i = 0; i < 4; ++i) {
            op[i] = wts[0] * (buf[i] + buf[i + 4 * D]) +
                    wts[1] * (buf[i + D] + buf[i + 3 * D]) +
                    wts[2] * buf[i + 2 * D];
        }
        *reinterpret_cast<float4*>(dst + y * PIT + x4) = o;
    }
}

// w_j = c_{j-1} - c_j over the 64x64 center, coalesced float4 stores.
__device__ __forceinline__ void emitw(const float* __restrict__ p,
                                      const float* __restrict__ c,
                                      float* __restrict__ o,
                                      int ty0, int tx0, int tid) {
    for (int it = tid; it < TILE * (TILE / 4); it += NT) {
        const int cg = it % (TILE / 4);
        const int r = it / (TILE / 4);
        const int y = CEN + r, x4 = CEN + cg * 4;
        const float4 a = *reinterpret_cast<const float4*>(p + y * PIT + x4);
        const float4 b = *reinterpret_cast<const float4*>(c + y * PIT + x4);
        *reinterpret_cast<float4*>(o + (size_t)(ty0 + r) * HW + tx0 + cg * 4) =
            make_float4(a.x - b.x, a.y - b.y, a.z - b.z, a.w - b.w);
    }
}

}  // namespace

extern __shared__ float g_smem[];

__global__ void __launch_bounds__(NT, 2)
uwt_kernel(const float* __restrict__ x, float* __restrict__ out) {
    float* X = g_smem;                 // c0, later c2
    float* Y = g_smem + Sg * PIT;      // H-conv temp
    float* Z = g_smem + 2 * Sg * PIT;  // c1, later c3

    const int tid = threadIdx.x;
    const int tx0 = (blockIdx.x & 15) * TILE;
    const int ty0 = (blockIdx.x >> 4) * TILE;
    const float* xb = x + (size_t)blockIdx.y * HW * HW;
    float* ob = out + (size_t)blockIdx.y * 4 * HW * HW;

    // Load c0 (96x96 with reflect padding) into X.
    for (int i = tid; i < Sg * Sg; i += NT) {
        const int y = i / Sg, xx = i - y * Sg;
        X[y * PIT + xx] =
            xb[(size_t)refl(ty0 - CEN + y) * HW + refl(tx0 - CEN + xx)];
    }
    __syncthreads();

    // Level 1 (d=1): need c1 on rows 4..91.
    hconv<1>(X, Y, 4, 88, tid);
    __syncthreads();
    wconv<1>(Y, Z, 4, 88, tid);  // c1 -> Z
    __syncthreads();
    emitw(X, Z, ob, ty0, tx0, tid);  // w1 (reads X,Z; overlaps next hconv safely)

    // Level 2 (d=2): need c2 on rows 8..87.
    hconv<2>(Z, Y, 8, 80, tid);
    __syncthreads();
    wconv<2>(Y, X, 8, 80, tid);  // c2 -> X (old c0 dead)
    __syncthreads();
    emitw(Z, X, ob + (size_t)HW * HW, ty0, tx0, tid);  // w2

    // Level 3 (d=4): need c3 on rows 16..79 (center only).
    hconv<4>(X, Y, 16, 64, tid);
    __syncthreads();
    wconv<4>(Y, Z, 16, 64, tid);  // c3 -> Z (old c1 dead)
    __syncthreads();

    // w3 = c2 - c3 (ch2) and c3 (ch3), fused emit.
    for (int it = tid; it < TILE * (TILE / 4); it += NT) {
        const int cg = it % (TILE / 4);
        const int r = it / (TILE / 4);
        const int y = CEN + r, x4 = CEN + cg * 4;
        const float4 a = *reinterpret_cast<const float4*>(X + y * PIT + x4);
        const float4 c = *reinterpret_cast<const float4*>(Z + y * PIT + x4);
        const size_t go = (size_t)(ty0 + r) * HW + tx0 + cg * 4;
        *reinterpret_cast<float4*>(ob + 2 * (size_t)HW * HW + go) =
            make_float4(a.x - c.x, a.y - c.y, a.z - c.z, a.w - c.w);
        *reinterpret_cast<float4*>(ob + 3 * (size_t)HW * HW + go) = c;
    }
}

extern "C" void kernel_launch(void* const* d_in, const int* in_sizes, int n_in,
                              void* d_out, int out_size) {
    const float* x = (const float*)d_in[0];
    float* out = (float*)d_out;
    const int smemBytes = 3 * Sg * PIT * (int)sizeof(float);  // 110592 B
    cudaFuncSetAttribute(uwt_kernel, cudaFuncAttributeMaxDynamicSharedMemorySize,
                         smemBytes);
    dim3 grid(256, 8);  // 16x16 tiles per image, 8 images
    uwt_kernel<<<grid, NT, smemBytes>>>(x, out);
}

// round 2
// speedup vs baseline: 1.4082x; 1.4082x over previous
#include <cuda_runtime.h>

// B3-spline undecimated wavelet transform (à trous), J=3, fully fused.
// Input:  x (8, 1024, 1024) fp32 -> Output: (8, 4, 1024, 1024) = [w1,w2,w3,c3]
//
// One CTA = one 64x64 output tile, 96x96 shared working grid (halo 16).
// 2 smem buffers (A = coeff plane, Y = H-conv temp), 72 KB -> 3 CTAs/SM.
// w-emits are fused into the W-conv pass (read-before-overwrite in place).

namespace {

constexpr int HW   = 1024;
constexpr int Sg   = 96;
constexpr int PIT  = 96;
constexpr int CEN  = 16;
constexpr int TILE = 64;
constexpr int NT   = 256;
constexpr float W0 = 0.0625f, W1 = 0.25f, W2 = 0.375f;

__device__ __forceinline__ int refl(int i) {
    if (i < 0) i = -i;
    if (i >= HW) i = 2 * HW - 2 - i;
    return i;
}

// Vertical 5-tap conv, dilation D. Items: 8 rows x 4 cols (float4),
// streaming 8+4D input rows -> (8+4D)/2 bytes read per output.
template <int D>
__device__ __forceinline__ void hconv(const float* __restrict__ src,
                                      float* __restrict__ dst,
                                      int r0, int nrb, int cg0, int ncg, int tid) {
    const int items = nrb * ncg;
    for (int it = tid; it < items; it += NT) {
        const int cg = cg0 + (it % ncg);
        const int y0 = r0 + (it / ncg) * 8;
        const float* sp = src + (y0 - 2 * D) * PIT + cg * 4;
        float4 acc[8];
#pragma unroll
        for (int i = 0; i < 8; ++i) acc[i] = make_float4(0.f, 0.f, 0.f, 0.f);
#pragma unroll
        for (int rr = 0; rr < 8 + 4 * D; ++rr) {
            const float4 v = *reinterpret_cast<const float4*>(sp + rr * PIT);
#pragma unroll
            for (int i = 0; i < 8; ++i) {
                const int t = rr - i;
                if (t >= 0 && t <= 4 * D && (t % D) == 0) {
                    const float w = (t == 0 || t == 4 * D) ? W0
                                  : (t == D || t == 3 * D) ? W1 : W2;
                    acc[i].x += w * v.x; acc[i].y += w * v.y;
                    acc[i].z += w * v.z; acc[i].w += w * v.w;
                }
            }
        }
        float* dp = dst + y0 * PIT + cg * 4;
#pragma unroll
        for (int i = 0; i < 8; ++i)
            *reinterpret_cast<float4*>(dp + i * PIT) = acc[i];
    }
}

// Horizontal 5-tap conv, dilation D. Items: 1 row x 8 cols.
// Fused emit: center items read prev coeff from A *before* overwriting it,
// store w = prev - c (and optionally c) to global.
// STOREC: write c_j into A (in place over c_{j-1}).  EMITC: also store c (level 3).
template <int D, bool STOREC, bool EMITC>
__device__ __forceinline__ void wconv(const float* __restrict__ src,
                                      float* A,
                                      int r0, int nrows, int cg80, int ncg8,
                                      float* __restrict__ owp,
                                      float* __restrict__ ocp,
                                      int ty0, int tx0, int tid) {
    const int items = nrows * ncg8;
    for (int it = tid; it < items; it += NT) {
        const int cg = cg80 + (it % ncg8);
        const int y  = r0 + it / ncg8;
        const int x8 = cg * 8;
        const float* row = src + y * PIT;
        float buf[8 + 4 * D];
        if (D == 1) {
#pragma unroll
            for (int j = 0; j < 6; ++j) {
                const float2 v = *reinterpret_cast<const float2*>(row + x8 - 2 + j * 2);
                buf[2 * j] = v.x; buf[2 * j + 1] = v.y;
            }
        } else {
#pragma unroll
            for (int j = 0; j < (8 + 4 * D) / 4; ++j) {
                const float4 v = *reinterpret_cast<const float4*>(row + x8 - 2 * D + j * 4);
                buf[4 * j] = v.x; buf[4 * j + 1] = v.y;
                buf[4 * j + 2] = v.z; buf[4 * j + 3] = v.w;
            }
        }
        float o[8];
#pragma unroll
        for (int i = 0; i < 8; ++i)
            o[i] = W0 * (buf[i] + buf[i + 4 * D]) +
                   W1 * (buf[i + D] + buf[i + 3 * D]) +
                   W2 * buf[i + 2 * D];

        const bool cen = (y >= CEN) & (y < CEN + TILE) & (x8 >= CEN) & (x8 < CEN + TILE);
        if (cen) {
            const float* ap = A + y * PIT + x8;  // prev coeff (read before write)
            const size_t go = (size_t)(ty0 + y - CEN) * HW + (tx0 + x8 - CEN);
            float* gp = owp + go;
            *reinterpret_cast<float4*>(gp) =
                make_float4(ap[0] - o[0], ap[1] - o[1], ap[2] - o[2], ap[3] - o[3]);
            *reinterpret_cast<float4*>(gp + 4) =
                make_float4(ap[4] - o[4], ap[5] - o[5], ap[6] - o[6], ap[7] - o[7]);
            if (EMITC) {
                float* gc = ocp + go;
                *reinterpret_cast<float4*>(gc)     = make_float4(o[0], o[1], o[2], o[3]);
                *reinterpret_cast<float4*>(gc + 4) = make_float4(o[4], o[5], o[6], o[7]);
            }
        }
        if (STOREC) {
            float* dp = A + y * PIT + x8;
            *reinterpret_cast<float4*>(dp)     = make_float4(o[0], o[1], o[2], o[3]);
            *reinterpret_cast<float4*>(dp + 4) = make_float4(o[4], o[5], o[6], o[7]);
        }
    }
}

}  // namespace

extern __shared__ float g_smem[];

__global__ void __launch_bounds__(NT, 3)
uwt_kernel(const float* __restrict__ x, float* __restrict__ out) {
    float* A = g_smem;              // coeff plane c_j (updated in place)
    float* Y = g_smem + Sg * PIT;   // H-conv temp

    const int tid = threadIdx.x;
    const int tx0 = (blockIdx.x & 15) * TILE;
    const int ty0 = (blockIdx.x >> 4) * TILE;
    const float* xb = x + (size_t)blockIdx.y * HW * HW;
    float* ob = out + (size_t)blockIdx.y * 4 * HW * HW;

    // Load c0 (96x96). Interior tiles: aligned float4, no reflection.
    if (tx0 > 0 && tx0 < HW - TILE && ty0 > 0 && ty0 < HW - TILE) {
        const float* gb = xb + (size_t)(ty0 - CEN) * HW + (tx0 - CEN);
        for (int i = tid; i < Sg * (Sg / 4); i += NT) {
            const int y = i / (Sg / 4), c4 = i % (Sg / 4);
            *reinterpret_cast<float4*>(A + y * PIT + c4 * 4) =
                *reinterpret_cast<const float4*>(gb + (size_t)y * HW + c4 * 4);
        }
    } else {
        for (int i = tid; i < Sg * Sg; i += NT) {
            const int y = i / Sg, xx = i - y * Sg;
            A[y * PIT + xx] =
                xb[(size_t)refl(ty0 - CEN + y) * HW + refl(tx0 - CEN + xx)];
        }
    }
    __syncthreads();

    // Level 1 (d=1): c1 on rows 4..91, valid cols 2..93.
    hconv<1>(A, Y, 4, 11, 0, 24, tid);
    __syncthreads();
    wconv<1, true, false>(Y, A, 4, 88, 0, 12, ob, nullptr, ty0, tx0, tid);
    __syncthreads();

    // Level 2 (d=2): c2 on rows 8..87, cols 8..87.
    hconv<2>(A, Y, 8, 10, 1, 22, tid);
    __syncthreads();
    wconv<2, true, false>(Y, A, 8, 80, 1, 10, ob + (size_t)HW * HW, nullptr,
                          ty0, tx0, tid);
    __syncthreads();

    // Level 3 (d=4): c3 on center only (rows/cols 16..79). Emit w3 + c3, no STS.
    hconv<4>(A, Y, 16, 8, 2, 20, tid);
    __syncthreads();
    wconv<4, false, true>(Y, A, 16, 64, 2, 8, ob + 2 * (size_t)HW * HW,
                          ob + 3 * (size_t)HW * HW, ty0, tx0, tid);
}

extern "C" void kernel_launch(void* const* d_in, const int* in_sizes, int n_in,
                              void* d_out, int out_size) {
    const float* x = (const float*)d_in[0];
    float* out = (float*)d_out;
    const int smemBytes = 2 * Sg * PIT * (int)sizeof(float);  // 73728 B
    cudaFuncSetAttribute(uwt_kernel, cudaFuncAttributeMaxDynamicSharedMemorySize,
                         smemBytes);
    dim3 grid(256, 8);
    uwt_kernel<<<grid, NT, smemBytes>>>(x, out);
}